// round 11
// baseline (speedup 1.0000x reference)
#include <cuda_runtime.h>
#include <cstdint>

#define D 128
#define D4 32          // D / 4
#define N_MAX 50000
#define NPB 32         // nodes per tile in the GEMM kernel
#define LN_EPS 1e-5f
#define GEMM_BLOCKS 444   // 3 per SM (148 SMs)

// Scratch: scattered neighbor sums (residual h added in the GEMM stage)
__device__ float g_agg[(size_t)N_MAX * D];

// ---------------------------------------------------------------------------
// Kernel 1: agg = 0  (scatter accumulates neighbor sums on top)
// ---------------------------------------------------------------------------
__global__ void k_zero_agg(int n4) {
    int i = blockIdx.x * blockDim.x + threadIdx.x;
    float4* agg4 = reinterpret_cast<float4*>(g_agg);
    if (i < n4) agg4[i] = make_float4(0.f, 0.f, 0.f, 0.f);
}

// ---------------------------------------------------------------------------
// Kernel 2: scatter-add  agg[dst[e]] += h[src[e]]   (one warp per edge)
// One red.global.add.v4.f32 (REDG.128) per lane — 4x fewer L2 atomic ops
// than scalar. Near the LTS byte-throughput floor (~614MB through L2).
// ---------------------------------------------------------------------------
__global__ __launch_bounds__(512)
void k_scatter_v4(const float4* __restrict__ h4,
                  const int* __restrict__ src,
                  const int* __restrict__ dst,
                  int E) {
    int warp_id = (blockIdx.x * blockDim.x + threadIdx.x) >> 5;
    int lane = threadIdx.x & 31;
    if (warp_id >= E) return;
    int s = __ldg(src + warp_id);       // warp-uniform (broadcast)
    int d = __ldg(dst + warp_id);
    float4 v = h4[(size_t)s * D4 + lane];
    float4* ap = reinterpret_cast<float4*>(g_agg) + (size_t)d * D4 + lane;
    asm volatile("red.global.add.v4.f32 [%0], {%1, %2, %3, %4};"
                 :: "l"(ap), "f"(v.x), "f"(v.y), "f"(v.z), "f"(v.w)
                 : "memory");
}

// ---------------------------------------------------------------------------
// Kernel 3: fused  x = agg + h ; y = x @ W^T + b ; LayerNorm ; ReLU
// Persistent blocks, 3 per SM. Thread j owns output column j; W row j in
// 64 regs of packed f32x2. Inner loop: fma.rn.f32x2 (2 MACs/instr).
// Residual add fused into staging. LN batched: warp-per-node shuffle.
// ---------------------------------------------------------------------------
__global__ __launch_bounds__(128, 3)
void k_gemm_ln_relu(const float4* __restrict__ h4,
                    const float* __restrict__ W,
                    const float* __restrict__ bias,
                    const float* __restrict__ gamma,
                    const float* __restrict__ beta,
                    float* __restrict__ out,
                    int N) {
    __shared__ float4 xs[NPB][D4];     // input tile (agg + h)
    __shared__ float  ys[NPB][D];      // pre-LN outputs

    const int j    = threadIdx.x;      // output column 0..127
    const int lane = j & 31;
    const int warp = j >> 5;

    // W row j as 32 x ulonglong2 (each .x/.y is a packed f32x2)
    ulonglong2 w[D4];
    const ulonglong2* W2 = reinterpret_cast<const ulonglong2*>(W);
#pragma unroll
    for (int k = 0; k < D4; k++) w[k] = W2[j * D4 + k];

    const float bj = bias[j];
    const float4 g4  = reinterpret_cast<const float4*>(gamma)[lane];
    const float4 be4 = reinterpret_cast<const float4*>(beta)[lane];

    const int numTiles = (N + NPB - 1) / NPB;
    for (int tile = blockIdx.x; tile < numTiles; tile += gridDim.x) {
        const int base  = tile * NPB;
        int valid = N - base; if (valid > NPB) valid = NPB;

        // Stage tile into shared with fused residual: xs = agg + h
        const float4* A4 = reinterpret_cast<const float4*>(g_agg) + (size_t)base * D4;
        const float4* H4 = h4 + (size_t)base * D4;
        for (int i = j; i < NPB * D4; i += 128) {
            int r = i >> 5;
            if (r < valid) {
                float4 a = A4[i];
                float4 hh = H4[i];
                a.x += hh.x; a.y += hh.y; a.z += hh.z; a.w += hh.w;
                xs[r][i & 31] = a;
            } else {
                xs[r][i & 31] = make_float4(0.f, 0.f, 0.f, 0.f);
            }
        }
        __syncthreads();

        // Compute y for every node in the tile (no syncs inside)
        for (int n = 0; n < NPB; n++) {
            unsigned long long a01a = 0ull, a23a = 0ull, a01b = 0ull, a23b = 0ull;
            const ulonglong2* xrow = reinterpret_cast<const ulonglong2*>(xs[n]);
#pragma unroll
            for (int k = 0; k < D4; k += 2) {
                ulonglong2 x0 = xrow[k];
                ulonglong2 x1 = xrow[k + 1];
                asm("fma.rn.f32x2 %0, %1, %2, %0;" : "+l"(a01a) : "l"(x0.x), "l"(w[k].x));
                asm("fma.rn.f32x2 %0, %1, %2, %0;" : "+l"(a23a) : "l"(x0.y), "l"(w[k].y));
                asm("fma.rn.f32x2 %0, %1, %2, %0;" : "+l"(a01b) : "l"(x1.x), "l"(w[k + 1].x));
                asm("fma.rn.f32x2 %0, %1, %2, %0;" : "+l"(a23b) : "l"(x1.y), "l"(w[k + 1].y));
            }
            unsigned int l0, h0, l1, h1, l2, h2, l3, h3;
            asm("mov.b64 {%0, %1}, %2;" : "=r"(l0), "=r"(h0) : "l"(a01a));
            asm("mov.b64 {%0, %1}, %2;" : "=r"(l1), "=r"(h1) : "l"(a23a));
            asm("mov.b64 {%0, %1}, %2;" : "=r"(l2), "=r"(h2) : "l"(a01b));
            asm("mov.b64 {%0, %1}, %2;" : "=r"(l3), "=r"(h3) : "l"(a23b));
            float y = ((__uint_as_float(l0) + __uint_as_float(h0)) +
                       (__uint_as_float(l1) + __uint_as_float(h1))) +
                      ((__uint_as_float(l2) + __uint_as_float(h2)) +
                       (__uint_as_float(l3) + __uint_as_float(h3))) + bj;
            ys[n][j] = y;
        }
        __syncthreads();

        // Batched LN + ReLU: warp handles nodes warp, warp+4, ...
        for (int n = warp; n < valid; n += 4) {
            float4 v = reinterpret_cast<const float4*>(ys[n])[lane];
            float s = (v.x + v.y) + (v.z + v.w);
            float q = (v.x * v.x + v.y * v.y) + (v.z * v.z + v.w * v.w);
#pragma unroll
            for (int o = 16; o > 0; o >>= 1) {
                s += __shfl_xor_sync(0xFFFFFFFFu, s, o);
                q += __shfl_xor_sync(0xFFFFFFFFu, q, o);
            }
            float mu  = s * (1.0f / D);
            float var = q * (1.0f / D) - mu * mu;
            float rs  = rsqrtf(var + LN_EPS);
            float4 o4;
            o4.x = fmaxf((v.x - mu) * rs * g4.x + be4.x, 0.f);
            o4.y = fmaxf((v.y - mu) * rs * g4.y + be4.y, 0.f);
            o4.z = fmaxf((v.z - mu) * rs * g4.z + be4.z, 0.f);
            o4.w = fmaxf((v.w - mu) * rs * g4.w + be4.w, 0.f);
            reinterpret_cast<float4*>(out + (size_t)(base + n) * D)[lane] = o4;
        }
        __syncthreads();   // xs/ys reused next tile
    }
}

// ---------------------------------------------------------------------------
extern "C" void kernel_launch(void* const* d_in, const int* in_sizes, int n_in,
                              void* d_out, int out_size) {
    const float* h     = (const float*)d_in[0];
    const int*   ei    = (const int*)d_in[1];   // [2, E] int32
    const float* W     = (const float*)d_in[2];
    const float* bias  = (const float*)d_in[3];
    const float* gamma = (const float*)d_in[4];
    const float* beta  = (const float*)d_in[5];
    float*       out   = (float*)d_out;

    const int N = in_sizes[0] / D;
    const int E = in_sizes[1] / 2;
    const int* src = ei;
    const int* dst = ei + E;

    // 1) agg = 0
    int n4 = N * D4;
    k_zero_agg<<<(n4 + 255) / 256, 256>>>(n4);

    // 2) vectorized scatter-add: 1 warp per edge, 16 edges per 512-thread block
    int blocks_sc = (E + 15) / 16;
    k_scatter_v4<<<blocks_sc, 512>>>(reinterpret_cast<const float4*>(h), src, dst, E);

    // 3) fused residual + linear + layernorm + relu
    k_gemm_ln_relu<<<GEMM_BLOCKS, 128>>>(reinterpret_cast<const float4*>(h),
                                         W, bias, gamma, beta, out, N);
}

// round 12
// speedup vs baseline: 1.0059x; 1.0059x over previous
#include <cuda_runtime.h>
#include <cstdint>

#define D 128
#define D4 32          // D / 4
#define N_MAX 50000
#define NPB 32         // nodes per tile in the GEMM kernel
#define LN_EPS 1e-5f
#define GEMM_BLOCKS 296   // 2 per SM (148 SMs)

// Scratch: scattered neighbor sums (residual h added in the GEMM stage)
__device__ float g_agg[(size_t)N_MAX * D];

// ---------------------------------------------------------------------------
// Kernel 1: agg = 0  (scatter accumulates neighbor sums on top)
// ---------------------------------------------------------------------------
__global__ void k_zero_agg(int n4) {
    int i = blockIdx.x * blockDim.x + threadIdx.x;
    float4* agg4 = reinterpret_cast<float4*>(g_agg);
    if (i < n4) agg4[i] = make_float4(0.f, 0.f, 0.f, 0.f);
}

// ---------------------------------------------------------------------------
// Kernel 2: scatter-add  agg[dst[e]] += h[src[e]]   (one warp per edge)
// One red.global.add.v4.f32 (REDG.128) per lane — 4x fewer L2 atomic ops
// than scalar. Near the LTS byte-throughput floor (~614MB through L2).
// ---------------------------------------------------------------------------
__global__ __launch_bounds__(512)
void k_scatter_v4(const float4* __restrict__ h4,
                  const int* __restrict__ src,
                  const int* __restrict__ dst,
                  int E) {
    int warp_id = (blockIdx.x * blockDim.x + threadIdx.x) >> 5;
    int lane = threadIdx.x & 31;
    if (warp_id >= E) return;
    int s = __ldg(src + warp_id);       // warp-uniform (broadcast)
    int d = __ldg(dst + warp_id);
    float4 v = h4[(size_t)s * D4 + lane];
    float4* ap = reinterpret_cast<float4*>(g_agg) + (size_t)d * D4 + lane;
    asm volatile("red.global.add.v4.f32 [%0], {%1, %2, %3, %4};"
                 :: "l"(ap), "f"(v.x), "f"(v.y), "f"(v.z), "f"(v.w)
                 : "memory");
}

// ---------------------------------------------------------------------------
// Kernel 3: fused  x = agg + h ; y = x @ W^T + b ; LayerNorm ; ReLU
// Persistent blocks, 2 per SM (proven best). Thread j owns output column j;
// W row j in 64 regs of packed f32x2. Inner loop: fma.rn.f32x2.
// Residual add fused into staging. LN batched: warp-per-node shuffle.
// ---------------------------------------------------------------------------
__global__ __launch_bounds__(128, 2)
void k_gemm_ln_relu(const float4* __restrict__ h4,
                    const float* __restrict__ W,
                    const float* __restrict__ bias,
                    const float* __restrict__ gamma,
                    const float* __restrict__ beta,
                    float* __restrict__ out,
                    int N) {
    __shared__ float4 xs[NPB][D4];     // input tile (agg + h)
    __shared__ float  ys[NPB][D];      // pre-LN outputs

    const int j    = threadIdx.x;      // output column 0..127
    const int lane = j & 31;
    const int warp = j >> 5;

    // W row j as 32 x ulonglong2 (each .x/.y is a packed f32x2)
    ulonglong2 w[D4];
    const ulonglong2* W2 = reinterpret_cast<const ulonglong2*>(W);
#pragma unroll
    for (int k = 0; k < D4; k++) w[k] = W2[j * D4 + k];

    const float bj = bias[j];
    const float4 g4  = reinterpret_cast<const float4*>(gamma)[lane];
    const float4 be4 = reinterpret_cast<const float4*>(beta)[lane];

    const int numTiles = (N + NPB - 1) / NPB;
    for (int tile = blockIdx.x; tile < numTiles; tile += gridDim.x) {
        const int base  = tile * NPB;
        int valid = N - base; if (valid > NPB) valid = NPB;

        // Stage tile into shared with fused residual: xs = agg + h
        const float4* A4 = reinterpret_cast<const float4*>(g_agg) + (size_t)base * D4;
        const float4* H4 = h4 + (size_t)base * D4;
        for (int i = j; i < NPB * D4; i += 128) {
            int r = i >> 5;
            if (r < valid) {
                float4 a = A4[i];
                float4 hh = H4[i];
                a.x += hh.x; a.y += hh.y; a.z += hh.z; a.w += hh.w;
                xs[r][i & 31] = a;
            } else {
                xs[r][i & 31] = make_float4(0.f, 0.f, 0.f, 0.f);
            }
        }
        __syncthreads();

        // Compute y for every node in the tile (no syncs inside)
        for (int n = 0; n < NPB; n++) {
            unsigned long long a01a = 0ull, a23a = 0ull, a01b = 0ull, a23b = 0ull;
            const ulonglong2* xrow = reinterpret_cast<const ulonglong2*>(xs[n]);
#pragma unroll
            for (int k = 0; k < D4; k += 2) {
                ulonglong2 x0 = xrow[k];
                ulonglong2 x1 = xrow[k + 1];
                asm("fma.rn.f32x2 %0, %1, %2, %0;" : "+l"(a01a) : "l"(x0.x), "l"(w[k].x));
                asm("fma.rn.f32x2 %0, %1, %2, %0;" : "+l"(a23a) : "l"(x0.y), "l"(w[k].y));
                asm("fma.rn.f32x2 %0, %1, %2, %0;" : "+l"(a01b) : "l"(x1.x), "l"(w[k + 1].x));
                asm("fma.rn.f32x2 %0, %1, %2, %0;" : "+l"(a23b) : "l"(x1.y), "l"(w[k + 1].y));
            }
            unsigned int l0, h0, l1, h1, l2, h2, l3, h3;
            asm("mov.b64 {%0, %1}, %2;" : "=r"(l0), "=r"(h0) : "l"(a01a));
            asm("mov.b64 {%0, %1}, %2;" : "=r"(l1), "=r"(h1) : "l"(a23a));
            asm("mov.b64 {%0, %1}, %2;" : "=r"(l2), "=r"(h2) : "l"(a01b));
            asm("mov.b64 {%0, %1}, %2;" : "=r"(l3), "=r"(h3) : "l"(a23b));
            float y = ((__uint_as_float(l0) + __uint_as_float(h0)) +
                       (__uint_as_float(l1) + __uint_as_float(h1))) +
                      ((__uint_as_float(l2) + __uint_as_float(h2)) +
                       (__uint_as_float(l3) + __uint_as_float(h3))) + bj;
            ys[n][j] = y;
        }
        __syncthreads();

        // Batched LN + ReLU: warp handles nodes warp, warp+4, ...
        for (int n = warp; n < valid; n += 4) {
            float4 v = reinterpret_cast<const float4*>(ys[n])[lane];
            float s = (v.x + v.y) + (v.z + v.w);
            float q = (v.x * v.x + v.y * v.y) + (v.z * v.z + v.w * v.w);
#pragma unroll
            for (int o = 16; o > 0; o >>= 1) {
                s += __shfl_xor_sync(0xFFFFFFFFu, s, o);
                q += __shfl_xor_sync(0xFFFFFFFFu, q, o);
            }
            float mu  = s * (1.0f / D);
            float var = q * (1.0f / D) - mu * mu;
            float rs  = rsqrtf(var + LN_EPS);
            float4 o4;
            o4.x = fmaxf((v.x - mu) * rs * g4.x + be4.x, 0.f);
            o4.y = fmaxf((v.y - mu) * rs * g4.y + be4.y, 0.f);
            o4.z = fmaxf((v.z - mu) * rs * g4.z + be4.z, 0.f);
            o4.w = fmaxf((v.w - mu) * rs * g4.w + be4.w, 0.f);
            reinterpret_cast<float4*>(out + (size_t)(base + n) * D)[lane] = o4;
        }
        __syncthreads();   // xs/ys reused next tile
    }
}

// ---------------------------------------------------------------------------
extern "C" void kernel_launch(void* const* d_in, const int* in_sizes, int n_in,
                              void* d_out, int out_size) {
    const float* h     = (const float*)d_in[0];
    const int*   ei    = (const int*)d_in[1];   // [2, E] int32
    const float* W     = (const float*)d_in[2];
    const float* bias  = (const float*)d_in[3];
    const float* gamma = (const float*)d_in[4];
    const float* beta  = (const float*)d_in[5];
    float*       out   = (float*)d_out;

    const int N = in_sizes[0] / D;
    const int E = in_sizes[1] / 2;
    const int* src = ei;
    const int* dst = ei + E;

    // 1) agg = 0
    int n4 = N * D4;
    k_zero_agg<<<(n4 + 255) / 256, 256>>>(n4);

    // 2) vectorized scatter-add: 1 warp per edge, 16 edges per 512-thread block
    int blocks_sc = (E + 15) / 16;
    k_scatter_v4<<<blocks_sc, 512>>>(reinterpret_cast<const float4*>(h), src, dst, E);

    // 3) fused residual + linear + layernorm + relu
    k_gemm_ln_relu<<<GEMM_BLOCKS, 128>>>(reinterpret_cast<const float4*>(h),
                                         W, bias, gamma, beta, out, N);
}

// round 13
// speedup vs baseline: 1.0690x; 1.0627x over previous
#include <cuda_runtime.h>
#include <cstdint>

#define D 128
#define D4 32          // D / 4
#define N_MAX 50000
#define NPB 32         // nodes per tile in the GEMM kernel
#define LN_EPS 1e-5f
#define GEMM_BLOCKS 296   // 2 per SM (148 SMs)

// Scratch: aggregated features (agg = h + sum_{e: dst=n} h[src])
__device__ float g_agg[(size_t)N_MAX * D];

// ---------------------------------------------------------------------------
// Kernel 1: agg = h  (residual pre-load; scatter accumulates on top)
// ---------------------------------------------------------------------------
__global__ void k_init_agg(const float4* __restrict__ h4, int n4) {
    int i = blockIdx.x * blockDim.x + threadIdx.x;
    float4* agg4 = reinterpret_cast<float4*>(g_agg);
    if (i < n4) agg4[i] = h4[i];
}

// ---------------------------------------------------------------------------
// Kernel 2: scatter-add  agg[dst[e]] += h[src[e]]   (one warp per edge)
// One red.global.add.v4.f32 (REDG.128) per lane — at the L2 atomic-BW floor.
// ---------------------------------------------------------------------------
__global__ __launch_bounds__(256)
void k_scatter_v4(const float4* __restrict__ h4,
                  const int* __restrict__ src,
                  const int* __restrict__ dst,
                  int E) {
    int warp_id = (blockIdx.x * blockDim.x + threadIdx.x) >> 5;
    int lane = threadIdx.x & 31;
    if (warp_id >= E) return;
    int s = __ldg(src + warp_id);       // warp-uniform (broadcast)
    int d = __ldg(dst + warp_id);
    float4 v = h4[(size_t)s * D4 + lane];
    float4* ap = reinterpret_cast<float4*>(g_agg) + (size_t)d * D4 + lane;
    asm volatile("red.global.add.v4.f32 [%0], {%1, %2, %3, %4};"
                 :: "l"(ap), "f"(v.x), "f"(v.y), "f"(v.z), "f"(v.w)
                 : "memory");
}

// ---------------------------------------------------------------------------
// Kernel 3: fused  y = agg @ W^T + b ; LayerNorm ; ReLU     (SPLIT-K by 2)
// 256 threads: thread (j = t&127, half = t>>7) computes K-range
// [half*64, half*64+64) of column j. Halves the serial FFMA2 chain per node
// and doubles warps/SMSP for latency hiding. Partials land in ys0/ys1;
// the LN phase fuses the combine (+bias) into its loads.
// ---------------------------------------------------------------------------
__global__ __launch_bounds__(256, 2)
void k_gemm_ln_relu(const float* __restrict__ W,
                    const float* __restrict__ bias,
                    const float* __restrict__ gamma,
                    const float* __restrict__ beta,
                    float* __restrict__ out,
                    int N) {
    __shared__ float4 xs[NPB][D4];     // input tile            (16 KB)
    __shared__ float  ys0[NPB][D];     // half-0 partials       (16 KB)
    __shared__ float  ys1[NPB][D];     // half-1 partials       (16 KB)

    const int t    = threadIdx.x;
    const int j    = t & 127;          // output column 0..127
    const int half = t >> 7;           // K-split half 0/1
    const int lane = t & 31;
    const int warp = t >> 5;           // 0..7

    // W row j, K-halves: 16 x ulonglong2 (each .x/.y is a packed f32x2)
    ulonglong2 w[16];
    const ulonglong2* W2 = reinterpret_cast<const ulonglong2*>(W);
#pragma unroll
    for (int k = 0; k < 16; k++) w[k] = W2[j * 32 + half * 16 + k];

    const float4 b4  = reinterpret_cast<const float4*>(bias)[lane];
    const float4 g4  = reinterpret_cast<const float4*>(gamma)[lane];
    const float4 be4 = reinterpret_cast<const float4*>(beta)[lane];

    float* ysH = half ? &ys1[0][0] : &ys0[0][0];

    const int numTiles = (N + NPB - 1) / NPB;
    for (int tile = blockIdx.x; tile < numTiles; tile += gridDim.x) {
        const int base  = tile * NPB;
        int valid = N - base; if (valid > NPB) valid = NPB;

        // Stage tile into shared (256 threads, 4 float4 each)
        const float4* X4 = reinterpret_cast<const float4*>(g_agg) + (size_t)base * D4;
        for (int i = t; i < NPB * D4; i += 256) {
            int r = i >> 5;
            xs[r][i & 31] = (r < valid) ? X4[i] : make_float4(0.f, 0.f, 0.f, 0.f);
        }
        __syncthreads();

        // Compute partial dot (K=64) for every node; no syncs inside
        for (int n = 0; n < NPB; n++) {
            unsigned long long a01a = 0ull, a23a = 0ull, a01b = 0ull, a23b = 0ull;
            const ulonglong2* xrow =
                reinterpret_cast<const ulonglong2*>(xs[n]) + half * 16;
#pragma unroll
            for (int k = 0; k < 16; k += 2) {
                ulonglong2 x0 = xrow[k];
                ulonglong2 x1 = xrow[k + 1];
                asm("fma.rn.f32x2 %0, %1, %2, %0;" : "+l"(a01a) : "l"(x0.x), "l"(w[k].x));
                asm("fma.rn.f32x2 %0, %1, %2, %0;" : "+l"(a23a) : "l"(x0.y), "l"(w[k].y));
                asm("fma.rn.f32x2 %0, %1, %2, %0;" : "+l"(a01b) : "l"(x1.x), "l"(w[k + 1].x));
                asm("fma.rn.f32x2 %0, %1, %2, %0;" : "+l"(a23b) : "l"(x1.y), "l"(w[k + 1].y));
            }
            unsigned int l0, h0, l1, h1, l2, h2, l3, h3;
            asm("mov.b64 {%0, %1}, %2;" : "=r"(l0), "=r"(h0) : "l"(a01a));
            asm("mov.b64 {%0, %1}, %2;" : "=r"(l1), "=r"(h1) : "l"(a23a));
            asm("mov.b64 {%0, %1}, %2;" : "=r"(l2), "=r"(h2) : "l"(a01b));
            asm("mov.b64 {%0, %1}, %2;" : "=r"(l3), "=r"(h3) : "l"(a23b));
            float y = ((__uint_as_float(l0) + __uint_as_float(h0)) +
                       (__uint_as_float(l1) + __uint_as_float(h1))) +
                      ((__uint_as_float(l2) + __uint_as_float(h2)) +
                       (__uint_as_float(l3) + __uint_as_float(h3)));
            ysH[n * D + j] = y;
        }
        __syncthreads();

        // Batched LN + ReLU: 8 warps, warp handles nodes warp, warp+8, ...
        // Combine split-K partials + bias fused into the loads.
        for (int n = warp; n < valid; n += 8) {
            float4 v0 = reinterpret_cast<const float4*>(ys0[n])[lane];
            float4 v1 = reinterpret_cast<const float4*>(ys1[n])[lane];
            float4 v;
            v.x = v0.x + v1.x + b4.x;
            v.y = v0.y + v1.y + b4.y;
            v.z = v0.z + v1.z + b4.z;
            v.w = v0.w + v1.w + b4.w;
            float s = (v.x + v.y) + (v.z + v.w);
            float q = (v.x * v.x + v.y * v.y) + (v.z * v.z + v.w * v.w);
#pragma unroll
            for (int o = 16; o > 0; o >>= 1) {
                s += __shfl_xor_sync(0xFFFFFFFFu, s, o);
                q += __shfl_xor_sync(0xFFFFFFFFu, q, o);
            }
            float mu  = s * (1.0f / D);
            float var = q * (1.0f / D) - mu * mu;
            float rs  = rsqrtf(var + LN_EPS);
            float4 o4;
            o4.x = fmaxf((v.x - mu) * rs * g4.x + be4.x, 0.f);
            o4.y = fmaxf((v.y - mu) * rs * g4.y + be4.y, 0.f);
            o4.z = fmaxf((v.z - mu) * rs * g4.z + be4.z, 0.f);
            o4.w = fmaxf((v.w - mu) * rs * g4.w + be4.w, 0.f);
            reinterpret_cast<float4*>(out + (size_t)(base + n) * D)[lane] = o4;
        }
        __syncthreads();   // xs/ys reused next tile
    }
}

// ---------------------------------------------------------------------------
extern "C" void kernel_launch(void* const* d_in, const int* in_sizes, int n_in,
                              void* d_out, int out_size) {
    const float* h     = (const float*)d_in[0];
    const int*   ei    = (const int*)d_in[1];   // [2, E] int32
    const float* W     = (const float*)d_in[2];
    const float* bias  = (const float*)d_in[3];
    const float* gamma = (const float*)d_in[4];
    const float* beta  = (const float*)d_in[5];
    float*       out   = (float*)d_out;

    const int N = in_sizes[0] / D;
    const int E = in_sizes[1] / 2;
    const int* src = ei;
    const int* dst = ei + E;

    // 1) agg = h
    int n4 = N * D4;
    k_init_agg<<<(n4 + 255) / 256, 256>>>(reinterpret_cast<const float4*>(h), n4);

    // 2) vectorized scatter-add: 1 warp per edge, 8 edges per 256-thread block
    int blocks_sc = (E + 7) / 8;
    k_scatter_v4<<<blocks_sc, 256>>>(reinterpret_cast<const float4*>(h), src, dst, E);

    // 3) fused linear (split-K) + layernorm + relu
    k_gemm_ln_relu<<<GEMM_BLOCKS, 256>>>(W, bias, gamma, beta, out, N);
}